// round 14
// baseline (speedup 1.0000x reference)
#include <cuda_runtime.h>
#include <cuda_bf16.h>
#include <cstdint>

// ---------------------------------------------------------------------------
// Wav2Vec2 Gumbel VQ via mma.sync bf16 (sm_100 baseline path).
//   logits = h @ W + b with bf16x3 split, 6 products (fp32-quality).
//   128-thread CTAs (tile 64x160, warp tile 32x80), 4 CTAs/SM single-buffered.
//   Chunk loads split into TWO cp.async groups by ks-half (cs 0/1 vs 2/3):
//   ks=1 data lands under ks=0 compute, halving the exposed load tail.
//   Ticketed merge: second half-CTA of each (tokens, group) pair does the
//   final argmax merge + histogram + codevector gather (no extra kernel).
// ---------------------------------------------------------------------------

namespace {
constexpr int kBT = 65536;
constexpr int kH  = 512;
constexpr int kV  = 320;
constexpr int kG  = 2;
constexpr int kGV = kG * kV;

constexpr int kMT = 64;                   // tokens per CTA
constexpr int kNT = 160;                  // logit cols per CTA (half group)
constexpr int kKC = 32;                   // K per chunk (2 mma k-steps)
constexpr int kChunks = kH / kKC;         // 16
constexpr int kThr = 128;                 // threads per CTA (4 warps)
constexpr int kTB  = kBT / kMT;           // 1024 token blocks

constexpr uint32_t kRowB   = 80;                           // 32 bf16 + 16B pad
constexpr uint32_t kAterm  = kMT * kRowB;                  // 5120
constexpr uint32_t kBterm  = kNT * kRowB;                  // 12800
constexpr uint32_t kStage  = 3 * kAterm + 3 * kBterm;      // 53760 (single buf)
constexpr uint32_t kHdr    = 2048;
constexpr uint32_t kSmemBytes = kHdr + kStage;             // 55808 (x4 = 223232)
}  // namespace

// global scratch (no cudaMalloc allowed)
__device__ __align__(256) __nv_bfloat16 g_h1[(size_t)kBT * kH];
__device__ __align__(256) __nv_bfloat16 g_h2[(size_t)kBT * kH];
__device__ __align__(256) __nv_bfloat16 g_h3[(size_t)kBT * kH];
__device__ __align__(256) __nv_bfloat16 g_w1t[kGV * kH];
__device__ __align__(256) __nv_bfloat16 g_w2t[kGV * kH];
__device__ __align__(256) __nv_bfloat16 g_w3t[kGV * kH];
__device__ float g_pval[4 * kBT];   // [(g*2+half)][token]
__device__ int   g_pidx[4 * kBT];
__device__ int   g_ticket[2 * kTB]; // per (token-block, group)
__device__ int   g_counts[kGV];

// ---------------- PTX helpers ----------------
__device__ __forceinline__ uint32_t smem_u32(const void* p) {
    uint32_t a;
    asm("{ .reg .u64 t; cvta.to.shared.u64 t, %1; cvt.u32.u64 %0, t; }"
        : "=r"(a) : "l"(p));
    return a;
}
__device__ __forceinline__ void cpa16(uint32_t s, const void* g) {
    asm volatile("cp.async.cg.shared.global [%0], [%1], 16;" :: "r"(s), "l"(g));
}
__device__ __forceinline__ void cpa_commit() {
    asm volatile("cp.async.commit_group;" ::: "memory");
}
__device__ __forceinline__ void ldsm4(uint32_t* d, uint32_t addr) {
    asm volatile("ldmatrix.sync.aligned.m8n8.x4.shared.b16 {%0,%1,%2,%3}, [%4];"
                 : "=r"(d[0]), "=r"(d[1]), "=r"(d[2]), "=r"(d[3]) : "r"(addr));
}
__device__ __forceinline__ void mma16816(float* c, const uint32_t* a,
                                         uint32_t b0, uint32_t b1) {
    asm volatile(
        "mma.sync.aligned.m16n8k16.row.col.f32.bf16.bf16.f32 "
        "{%0,%1,%2,%3}, {%4,%5,%6,%7}, {%8,%9}, {%0,%1,%2,%3};"
        : "+f"(c[0]), "+f"(c[1]), "+f"(c[2]), "+f"(c[3])
        : "r"(a[0]), "r"(a[1]), "r"(a[2]), "r"(a[3]), "r"(b0), "r"(b1));
}

// ---------------- split kernels ----------------
__device__ __forceinline__ uint32_t pk2(__nv_bfloat16 x, __nv_bfloat16 y) {
    return (uint32_t)__bfloat16_as_ushort(x) |
           ((uint32_t)__bfloat16_as_ushort(y) << 16);
}

__global__ void __launch_bounds__(256) split_h_kernel(const float* __restrict__ h) {
    size_t i = (size_t)blockIdx.x * 256 + threadIdx.x;   // one float4 each
    float4 x = ((const float4*)h)[i];
    float v[4] = {x.x, x.y, x.z, x.w};
    __nv_bfloat16 a[4], b[4], c[4];
#pragma unroll
    for (int j = 0; j < 4; j++) {
        a[j] = __float2bfloat16_rn(v[j]);
        float r = v[j] - __bfloat162float(a[j]);
        b[j] = __float2bfloat16_rn(r);
        float r2 = r - __bfloat162float(b[j]);
        c[j] = __float2bfloat16_rn(r2);
    }
    ((uint2*)g_h1)[i] = make_uint2(pk2(a[0], a[1]), pk2(a[2], a[3]));
    ((uint2*)g_h2)[i] = make_uint2(pk2(b[0], b[1]), pk2(b[2], b[3]));
    ((uint2*)g_h3)[i] = make_uint2(pk2(c[0], c[1]), pk2(c[2], c[3]));
}

__global__ void __launch_bounds__(256) split_w_kernel(const float* __restrict__ W) {
    int idx = blockIdx.x * 256 + threadIdx.x;   // over 512*640
    int k = idx / kGV;
    int n = idx - k * kGV;
    float v = W[idx];
    __nv_bfloat16 a = __float2bfloat16_rn(v);
    float r = v - __bfloat162float(a);
    __nv_bfloat16 b = __float2bfloat16_rn(r);
    float r2 = r - __bfloat162float(b);
    __nv_bfloat16 c = __float2bfloat16_rn(r2);
    size_t o = (size_t)n * kH + k;               // transposed [n][k]
    g_w1t[o] = a; g_w2t[o] = b; g_w3t[o] = c;
}

// ---------------- main tensor kernel loader ----------------
// Loads the cs-pair {2h, 2h+1} (bytes [32h, 32h+32) of each 80B row) for
// chunk c: the exact data consumed by compute k-step ks==h.
__device__ __forceinline__ void load_half(int c, int h, int m0, int nbase,
                                          uint32_t As, uint32_t Bsm, int tid) {
    // A: 3 terms x 64 rows x 2 cs = 384 cp.async (3 per thread)
#pragma unroll
    for (int t = 0; t < 3; ++t) {
        const __nv_bfloat16* hp = (t == 0) ? g_h1 : (t == 1) ? g_h2 : g_h3;
        int row = tid >> 1, cs = 2 * h + (tid & 1);
        const void* gp = hp + ((size_t)(m0 + row) * kH + c * kKC + cs * 8);
        cpa16(As + t * kAterm + row * kRowB + cs * 16, gp);
    }
    // B: 3 terms x 160 rows x 2 cs = 960 cp.async (<=8 per thread)
#pragma unroll
    for (int t = 0; t < 3; ++t) {
        const __nv_bfloat16* wp = (t == 0) ? g_w1t : (t == 1) ? g_w2t : g_w3t;
#pragma unroll
        for (int i = 0; i < 3; ++i) {
            int idx = tid + i * kThr;        // 0..383, need < 320
            if (idx < 320) {
                int row = idx >> 1, cs = 2 * h + (idx & 1);
                const void* gp =
                    wp + ((size_t)(nbase + row) * kH + c * kKC + cs * 8);
                cpa16(Bsm + t * kBterm + row * kRowB + cs * 16, gp);
            }
        }
    }
    cpa_commit();
}

__global__ void __launch_bounds__(kThr, 4)
vq_mma(const float* __restrict__ bias,
       const float* __restrict__ cb,      // [640][128]
       float* __restrict__ out)           // [BT][256]
{
    extern __shared__ __align__(256) char smem_raw[];
    const uint32_t sbase = smem_u32(smem_raw);
    float* red_val = (float*)smem_raw;                 // [64][2]   @0
    int*   red_idx = (int*)(smem_raw + 512);           // [64][2]   @512
    float* bias_s  = (float*)(smem_raw + 1024);        // [160]     @1024
    int*   idx_s   = (int*)(smem_raw + 1664);          // [64]      @1664
    __shared__ int is_merger;
    const uint32_t As  = sbase + kHdr;                 // A tiles (single buf)
    const uint32_t Bsm = As + 3 * kAterm;              // B tiles (single buf)

    const int tid  = threadIdx.x;
    const int warp = tid >> 5;
    const int lane = tid & 31;
    const int mw   = warp >> 1;            // 0..1 (32 rows each)
    const int nw   = warp & 1;             // 0..1 (80 cols each)
    const int gID  = lane >> 2;
    const int tig  = lane & 3;
    const int bx   = blockIdx.x;
    const int half = bx & 1;
    const int g    = (bx >> 1) & 1;
    const int m0   = (bx >> 2) * kMT;
    const int nbase = g * kV + half * kNT; // B row base

    for (int i = tid; i < kNT; i += kThr) bias_s[i] = bias[nbase + i];

    load_half(0, 0, m0, nbase, As, Bsm, tid);
    load_half(0, 1, m0, nbase, As, Bsm, tid);

    float acc[2][10][4];
#pragma unroll
    for (int mf = 0; mf < 2; ++mf)
#pragma unroll
        for (int nf = 0; nf < 10; ++nf)
#pragma unroll
            for (int q = 0; q < 4; ++q) acc[mf][nf][q] = 0.f;

    const int g2 = lane >> 3, rr = lane & 7;

    for (int c = 0; c < kChunks; ++c) {
#pragma unroll
        for (int ks = 0; ks < 2; ++ks) {
            // ks==0: wait for group(cs0/1) only; ks==1: all groups.
            if (ks == 0)
                asm volatile("cp.async.wait_group 1;" ::: "memory");
            else
                asm volatile("cp.async.wait_group 0;" ::: "memory");
            __syncthreads();

            const uint32_t arow = (uint32_t)(mw * 32 + (g2 & 1) * 8 + rr);
            const uint32_t koA  = (uint32_t)(ks * 32 + (g2 >> 1) * 16);
            const uint32_t brow = (uint32_t)(nw * 80 + (g2 >> 1) * 8 + rr);
            const uint32_t koB  = (uint32_t)(ks * 32 + (g2 & 1) * 16);

            // Load ALL A fragments once per ks (6 ldsm; 24 regs live).
            uint32_t a[3][2][4];
#pragma unroll
            for (int t = 0; t < 3; ++t)
#pragma unroll
                for (int mf = 0; mf < 2; ++mf)
                    ldsm4(a[t][mf],
                          As + t * kAterm + (arow + mf * 16) * kRowB + koA);

            // bt -> j -> at: each b[4] ldsm feeds up to 6 MMAs, then dies.
#pragma unroll
            for (int bt = 0; bt < 3; ++bt) {
                const int nat = 3 - bt;     // products with at+bt<=2
#pragma unroll
                for (int j = 0; j < 5; ++j) {
                    uint32_t b[4];
                    ldsm4(b, Bsm + bt * kBterm + (brow + j * 16) * kRowB + koB);
#pragma unroll
                    for (int at = 0; at < 3; ++at) {
                        if (at >= nat) break;
#pragma unroll
                        for (int mf = 0; mf < 2; ++mf) {
                            mma16816(acc[mf][2 * j],     a[at][mf], b[0], b[1]);
                            mma16816(acc[mf][2 * j + 1], a[at][mf], b[2], b[3]);
                        }
                    }
                }
            }
        }
        __syncthreads();                    // all reads of buffer complete
        if (c + 1 < kChunks) {
            load_half(c + 1, 0, m0, nbase, As, Bsm, tid);
            load_half(c + 1, 1, m0, nbase, As, Bsm, tid);
        }
    }

    // ---- fused bias + local argmax over this CTA's 160 cols ----
#pragma unroll
    for (int mf = 0; mf < 2; ++mf) {
#pragma unroll
        for (int hi = 0; hi < 2; ++hi) {
            float bv = -3.4e38f;
            int bi = 0;
#pragma unroll
            for (int nf = 0; nf < 10; ++nf) {
#pragma unroll
                for (int cc = 0; cc < 2; ++cc) {
                    int col = nw * 80 + nf * 8 + tig * 2 + cc;
                    float v = acc[mf][nf][hi * 2 + cc] + bias_s[col];
                    if (v > bv) { bv = v; bi = col; }
                }
            }
#pragma unroll
            for (int d = 1; d < 4; d <<= 1) {
                float ov = __shfl_xor_sync(0xFFFFFFFFu, bv, d);
                int   oi = __shfl_xor_sync(0xFFFFFFFFu, bi, d);
                if (ov > bv || (ov == bv && oi < bi)) { bv = ov; bi = oi; }
            }
            if (tig == 0) {
                int row = mw * 32 + mf * 16 + hi * 8 + gID;
                red_val[row * 2 + nw] = bv;
                red_idx[row * 2 + nw] = bi;
            }
        }
    }
    __syncthreads();

    // ---- publish this half's partial (max, idx) per token ----
    if (tid < kMT) {
        float v0 = red_val[tid * 2], v1 = red_val[tid * 2 + 1];
        int   i0 = red_idx[tid * 2], i1 = red_idx[tid * 2 + 1];
        float bv = v0; int bi = i0;
        if (v1 > bv || (v1 == bv && i1 < bi)) { bv = v1; bi = i1; }
        int slot = (g * 2 + half) * kBT + m0 + tid;
        g_pval[slot] = bv;
        g_pidx[slot] = half * kNT + bi;     // group-local index 0..319
    }
    __threadfence();
    __syncthreads();

    // ---- ticket: the SECOND half-CTA of (token-block, g) merges ----
    if (tid == 0)
        is_merger = (atomicAdd(&g_ticket[(m0 / kMT) * 2 + g], 1) == 1);
    __syncthreads();
    if (!is_merger) return;
    __threadfence();

    if (tid < kMT) {
        int tok = m0 + tid;
        float v0 = g_pval[(g * 2 + 0) * kBT + tok];
        float v1 = g_pval[(g * 2 + 1) * kBT + tok];
        int   i0 = g_pidx[(g * 2 + 0) * kBT + tok];
        int   i1 = g_pidx[(g * 2 + 1) * kBT + tok];
        int bi = (v1 > v0) ? i1 : i0;       // tie -> half0 (lower idx)
        idx_s[tid] = bi;
        atomicAdd(&g_counts[g * kV + bi], 1);
    }
    __syncthreads();

    // ---- coalesced codevector gather (this group's half of each out row) ----
    const float4* cbv  = (const float4*)cb;
    float4*       outv = (float4*)out;
#pragma unroll
    for (int i = 0; i < 16; ++i) {
        int e = tid + i * kThr;             // 0..2047
        int m = e >> 5, j = e & 31;
        int vi = idx_s[m];
        outv[(size_t)(m0 + m) * 64 + g * 32 + j] =
            cbv[(size_t)(g * kV + vi) * 32 + j];
    }
}

// ---------------- tiny kernels ----------------
__global__ void vq_zero() {
    int i = blockIdx.x * 256 + threadIdx.x;
    if (i < kGV) g_counts[i] = 0;
    if (i < 2 * kTB) g_ticket[i] = 0;
}

__global__ void vq_ppl(float* __restrict__ out, int out_size) {
    __shared__ float terms[kGV];
    int t = threadIdx.x;               // 320 threads
    for (int g = 0; g < kG; g++) {
        float m = (float)g_counts[g * kV + t] / (float)kBT;
        terms[g * kV + t] = m * logf(m + 1e-7f);
    }
    __syncthreads();
    if (t == 0) {
        float p = 0.f;
        for (int g = 0; g < kG; g++) {
            float s = 0.f;
            for (int v = 0; v < kV; v++) s += terms[g * kV + v];
            p += expf(-s);
        }
        out[out_size - 1] = p;
    }
}

extern "C" void kernel_launch(void* const* d_in, const int* in_sizes, int n_in,
                              void* d_out, int out_size) {
    (void)in_sizes; (void)n_in;
    const float* hid  = (const float*)d_in[0];
    const float* W    = (const float*)d_in[1];
    const float* bias = (const float*)d_in[2];
    const float* cb   = (const float*)d_in[3];
    float* out = (float*)d_out;

    cudaFuncSetAttribute(vq_mma, cudaFuncAttributeMaxDynamicSharedMemorySize,
                         kSmemBytes);

    vq_zero<<<(2 * kTB + 255) / 256, 256>>>();
    split_h_kernel<<<(kBT * kH / 4) / 256, 256>>>(hid);
    split_w_kernel<<<(kH * kGV) / 256, 256>>>(W);
    vq_mma<<<kTB * 4, kThr, kSmemBytes>>>(bias, cb, out);
    vq_ppl<<<1, kV>>>(out, out_size);
}

// round 15
// speedup vs baseline: 1.2088x; 1.2088x over previous
#include <cuda_runtime.h>
#include <cuda_bf16.h>
#include <cstdint>

// ---------------------------------------------------------------------------
// Wav2Vec2 Gumbel VQ via mma.sync bf16 (sm_100 baseline path).
//   logits = h @ W + b with bf16x3 split, 6 products (fp32-quality).
//   R12 mainloop: 128-thread CTAs (tile 64x160, warp tile 32x80), 4 CTAs/SM,
//   single-buffered, ONE load_chunk + ONE barrier pair per chunk.
//   R13 epilogue: ticketed merge — second half-CTA of each (tokens, group)
//   pair does final argmax merge + histogram + codevector gather.
// ---------------------------------------------------------------------------

namespace {
constexpr int kBT = 65536;
constexpr int kH  = 512;
constexpr int kV  = 320;
constexpr int kG  = 2;
constexpr int kGV = kG * kV;

constexpr int kMT = 64;                   // tokens per CTA
constexpr int kNT = 160;                  // logit cols per CTA (half group)
constexpr int kKC = 32;                   // K per chunk (2 mma k-steps)
constexpr int kChunks = kH / kKC;         // 16
constexpr int kThr = 128;                 // threads per CTA (4 warps)
constexpr int kTB  = kBT / kMT;           // 1024 token blocks

constexpr uint32_t kRowB   = 80;                           // 32 bf16 + 16B pad
constexpr uint32_t kAterm  = kMT * kRowB;                  // 5120
constexpr uint32_t kBterm  = kNT * kRowB;                  // 12800
constexpr uint32_t kStage  = 3 * kAterm + 3 * kBterm;      // 53760 (single buf)
constexpr uint32_t kHdr    = 2048;
constexpr uint32_t kSmemBytes = kHdr + kStage;             // 55808 (x4 = 223232)
}  // namespace

// global scratch (no cudaMalloc allowed)
__device__ __align__(256) __nv_bfloat16 g_h1[(size_t)kBT * kH];
__device__ __align__(256) __nv_bfloat16 g_h2[(size_t)kBT * kH];
__device__ __align__(256) __nv_bfloat16 g_h3[(size_t)kBT * kH];
__device__ __align__(256) __nv_bfloat16 g_w1t[kGV * kH];
__device__ __align__(256) __nv_bfloat16 g_w2t[kGV * kH];
__device__ __align__(256) __nv_bfloat16 g_w3t[kGV * kH];
__device__ float g_pval[4 * kBT];   // [(g*2+half)][token]
__device__ int   g_pidx[4 * kBT];
__device__ int   g_ticket[2 * kTB]; // per (token-block, group)
__device__ int   g_counts[kGV];

// ---------------- PTX helpers ----------------
__device__ __forceinline__ uint32_t smem_u32(const void* p) {
    uint32_t a;
    asm("{ .reg .u64 t; cvta.to.shared.u64 t, %1; cvt.u32.u64 %0, t; }"
        : "=r"(a) : "l"(p));
    return a;
}
__device__ __forceinline__ void cpa16(uint32_t s, const void* g) {
    asm volatile("cp.async.cg.shared.global [%0], [%1], 16;" :: "r"(s), "l"(g));
}
__device__ __forceinline__ void cpa_commit() {
    asm volatile("cp.async.commit_group;" ::: "memory");
}
__device__ __forceinline__ void ldsm4(uint32_t* d, uint32_t addr) {
    asm volatile("ldmatrix.sync.aligned.m8n8.x4.shared.b16 {%0,%1,%2,%3}, [%4];"
                 : "=r"(d[0]), "=r"(d[1]), "=r"(d[2]), "=r"(d[3]) : "r"(addr));
}
__device__ __forceinline__ void mma16816(float* c, const uint32_t* a,
                                         uint32_t b0, uint32_t b1) {
    asm volatile(
        "mma.sync.aligned.m16n8k16.row.col.f32.bf16.bf16.f32 "
        "{%0,%1,%2,%3}, {%4,%5,%6,%7}, {%8,%9}, {%0,%1,%2,%3};"
        : "+f"(c[0]), "+f"(c[1]), "+f"(c[2]), "+f"(c[3])
        : "r"(a[0]), "r"(a[1]), "r"(a[2]), "r"(a[3]), "r"(b0), "r"(b1));
}

// ---------------- split kernels ----------------
__device__ __forceinline__ uint32_t pk2(__nv_bfloat16 x, __nv_bfloat16 y) {
    return (uint32_t)__bfloat16_as_ushort(x) |
           ((uint32_t)__bfloat16_as_ushort(y) << 16);
}

__global__ void __launch_bounds__(256) split_h_kernel(const float* __restrict__ h) {
    size_t i = (size_t)blockIdx.x * 256 + threadIdx.x;   // one float4 each
    float4 x = ((const float4*)h)[i];
    float v[4] = {x.x, x.y, x.z, x.w};
    __nv_bfloat16 a[4], b[4], c[4];
#pragma unroll
    for (int j = 0; j < 4; j++) {
        a[j] = __float2bfloat16_rn(v[j]);
        float r = v[j] - __bfloat162float(a[j]);
        b[j] = __float2bfloat16_rn(r);
        float r2 = r - __bfloat162float(b[j]);
        c[j] = __float2bfloat16_rn(r2);
    }
    ((uint2*)g_h1)[i] = make_uint2(pk2(a[0], a[1]), pk2(a[2], a[3]));
    ((uint2*)g_h2)[i] = make_uint2(pk2(b[0], b[1]), pk2(b[2], b[3]));
    ((uint2*)g_h3)[i] = make_uint2(pk2(c[0], c[1]), pk2(c[2], c[3]));
}

__global__ void __launch_bounds__(256) split_w_kernel(const float* __restrict__ W) {
    int idx = blockIdx.x * 256 + threadIdx.x;   // over 512*640
    int k = idx / kGV;
    int n = idx - k * kGV;
    float v = W[idx];
    __nv_bfloat16 a = __float2bfloat16_rn(v);
    float r = v - __bfloat162float(a);
    __nv_bfloat16 b = __float2bfloat16_rn(r);
    float r2 = r - __bfloat162float(b);
    __nv_bfloat16 c = __float2bfloat16_rn(r2);
    size_t o = (size_t)n * kH + k;               // transposed [n][k]
    g_w1t[o] = a; g_w2t[o] = b; g_w3t[o] = c;
}

// ---------------- main tensor kernel loader (R12) ----------------
__device__ __forceinline__ void load_chunk(int c, int m0, int nbase,
                                           uint32_t As, uint32_t Bsm, int tid) {
    // A: 3 terms x 64 rows x 4 x 16B = 768 cp.async (6 per thread)
#pragma unroll
    for (int t = 0; t < 3; ++t) {
        const __nv_bfloat16* hp = (t == 0) ? g_h1 : (t == 1) ? g_h2 : g_h3;
#pragma unroll
        for (int i = 0; i < 2; ++i) {
            int idx = tid + i * kThr;        // 0..255
            int row = idx >> 2, cs = idx & 3;
            const void* gp = hp + ((size_t)(m0 + row) * kH + c * kKC + cs * 8);
            cpa16(As + t * kAterm + row * kRowB + cs * 16, gp);
        }
    }
    // B: 3 terms x 160 rows x 4 x 16B = 1920 cp.async (15 per thread)
#pragma unroll
    for (int t = 0; t < 3; ++t) {
        const __nv_bfloat16* wp = (t == 0) ? g_w1t : (t == 1) ? g_w2t : g_w3t;
#pragma unroll
        for (int i = 0; i < 5; ++i) {
            int idx = tid + i * kThr;        // 0..639
            int row = idx >> 2, cs = idx & 3;
            const void* gp = wp + ((size_t)(nbase + row) * kH + c * kKC + cs * 8);
            cpa16(Bsm + t * kBterm + row * kRowB + cs * 16, gp);
        }
    }
    cpa_commit();
}

__global__ void __launch_bounds__(kThr, 4)
vq_mma(const float* __restrict__ bias,
       const float* __restrict__ cb,      // [640][128]
       float* __restrict__ out)           // [BT][256]
{
    extern __shared__ __align__(256) char smem_raw[];
    const uint32_t sbase = smem_u32(smem_raw);
    float* red_val = (float*)smem_raw;                 // [64][2]   @0
    int*   red_idx = (int*)(smem_raw + 512);           // [64][2]   @512
    float* bias_s  = (float*)(smem_raw + 1024);        // [160]     @1024
    int*   idx_s   = (int*)(smem_raw + 1664);          // [64]      @1664
    __shared__ int is_merger;
    const uint32_t As  = sbase + kHdr;                 // A tiles (single buf)
    const uint32_t Bsm = As + 3 * kAterm;              // B tiles (single buf)

    const int tid  = threadIdx.x;
    const int warp = tid >> 5;
    const int lane = tid & 31;
    const int mw   = warp >> 1;            // 0..1 (32 rows each)
    const int nw   = warp & 1;             // 0..1 (80 cols each)
    const int gID  = lane >> 2;
    const int tig  = lane & 3;
    const int bx   = blockIdx.x;
    const int half = bx & 1;
    const int g    = (bx >> 1) & 1;
    const int m0   = (bx >> 2) * kMT;
    const int nbase = g * kV + half * kNT; // B row base

    for (int i = tid; i < kNT; i += kThr) bias_s[i] = bias[nbase + i];

    load_chunk(0, m0, nbase, As, Bsm, tid);

    float acc[2][10][4];
#pragma unroll
    for (int mf = 0; mf < 2; ++mf)
#pragma unroll
        for (int nf = 0; nf < 10; ++nf)
#pragma unroll
            for (int q = 0; q < 4; ++q) acc[mf][nf][q] = 0.f;

    const int g2 = lane >> 3, rr = lane & 7;

    for (int c = 0; c < kChunks; ++c) {
        asm volatile("cp.async.wait_group 0;" ::: "memory");
        __syncthreads();

#pragma unroll
        for (int ks = 0; ks < 2; ++ks) {
            const uint32_t arow = (uint32_t)(mw * 32 + (g2 & 1) * 8 + rr);
            const uint32_t koA  = (uint32_t)(ks * 32 + (g2 >> 1) * 16);
            const uint32_t brow = (uint32_t)(nw * 80 + (g2 >> 1) * 8 + rr);
            const uint32_t koB  = (uint32_t)(ks * 32 + (g2 & 1) * 16);

            // Load ALL A fragments once per ks (6 ldsm; 24 regs live).
            uint32_t a[3][2][4];
#pragma unroll
            for (int t = 0; t < 3; ++t)
#pragma unroll
                for (int mf = 0; mf < 2; ++mf)
                    ldsm4(a[t][mf],
                          As + t * kAterm + (arow + mf * 16) * kRowB + koA);

            // bt -> j -> at: each b[4] ldsm feeds up to 6 MMAs, then dies.
#pragma unroll
            for (int bt = 0; bt < 3; ++bt) {
                const int nat = 3 - bt;     // products with at+bt<=2
#pragma unroll
                for (int j = 0; j < 5; ++j) {
                    uint32_t b[4];
                    ldsm4(b, Bsm + bt * kBterm + (brow + j * 16) * kRowB + koB);
#pragma unroll
                    for (int at = 0; at < 3; ++at) {
                        if (at >= nat) break;
#pragma unroll
                        for (int mf = 0; mf < 2; ++mf) {
                            mma16816(acc[mf][2 * j],     a[at][mf], b[0], b[1]);
                            mma16816(acc[mf][2 * j + 1], a[at][mf], b[2], b[3]);
                        }
                    }
                }
            }
        }
        __syncthreads();
        if (c + 1 < kChunks)
            load_chunk(c + 1, m0, nbase, As, Bsm, tid);
    }

    // ---- fused bias + local argmax over this CTA's 160 cols ----
#pragma unroll
    for (int mf = 0; mf < 2; ++mf) {
#pragma unroll
        for (int hi = 0; hi < 2; ++hi) {
            float bv = -3.4e38f;
            int bi = 0;
#pragma unroll
            for (int nf = 0; nf < 10; ++nf) {
#pragma unroll
                for (int cc = 0; cc < 2; ++cc) {
                    int col = nw * 80 + nf * 8 + tig * 2 + cc;
                    float v = acc[mf][nf][hi * 2 + cc] + bias_s[col];
                    if (v > bv) { bv = v; bi = col; }
                }
            }
#pragma unroll
            for (int d = 1; d < 4; d <<= 1) {
                float ov = __shfl_xor_sync(0xFFFFFFFFu, bv, d);
                int   oi = __shfl_xor_sync(0xFFFFFFFFu, bi, d);
                if (ov > bv || (ov == bv && oi < bi)) { bv = ov; bi = oi; }
            }
            if (tig == 0) {
                int row = mw * 32 + mf * 16 + hi * 8 + gID;
                red_val[row * 2 + nw] = bv;
                red_idx[row * 2 + nw] = bi;
            }
        }
    }
    __syncthreads();

    // ---- publish this half's partial (max, idx) per token ----
    if (tid < kMT) {
        float v0 = red_val[tid * 2], v1 = red_val[tid * 2 + 1];
        int   i0 = red_idx[tid * 2], i1 = red_idx[tid * 2 + 1];
        float bv = v0; int bi = i0;
        if (v1 > bv || (v1 == bv && i1 < bi)) { bv = v1; bi = i1; }
        int slot = (g * 2 + half) * kBT + m0 + tid;
        g_pval[slot] = bv;
        g_pidx[slot] = half * kNT + bi;     // group-local index 0..319
    }
    __threadfence();
    __syncthreads();

    // ---- ticket: the SECOND half-CTA of (token-block, g) merges ----
    if (tid == 0)
        is_merger = (atomicAdd(&g_ticket[(m0 / kMT) * 2 + g], 1) == 1);
    __syncthreads();
    if (!is_merger) return;
    __threadfence();

    if (tid < kMT) {
        int tok = m0 + tid;
        float v0 = g_pval[(g * 2 + 0) * kBT + tok];
        float v1 = g_pval[(g * 2 + 1) * kBT + tok];
        int   i0 = g_pidx[(g * 2 + 0) * kBT + tok];
        int   i1 = g_pidx[(g * 2 + 1) * kBT + tok];
        int bi = (v1 > v0) ? i1 : i0;       // tie -> half0 (lower idx)
        idx_s[tid] = bi;
        atomicAdd(&g_counts[g * kV + bi], 1);
    }
    __syncthreads();

    // ---- coalesced codevector gather (this group's half of each out row) ----
    const float4* cbv  = (const float4*)cb;
    float4*       outv = (float4*)out;
#pragma unroll
    for (int i = 0; i < 16; ++i) {
        int e = tid + i * kThr;             // 0..2047
        int m = e >> 5, j = e & 31;
        int vi = idx_s[m];
        outv[(size_t)(m0 + m) * 64 + g * 32 + j] =
            cbv[(size_t)(g * kV + vi) * 32 + j];
    }
}

// ---------------- tiny kernels ----------------
__global__ void vq_zero() {
    int i = blockIdx.x * 256 + threadIdx.x;
    if (i < kGV) g_counts[i] = 0;
    if (i < 2 * kTB) g_ticket[i] = 0;
}

__global__ void vq_ppl(float* __restrict__ out, int out_size) {
    __shared__ float terms[kGV];
    int t = threadIdx.x;               // 320 threads
    for (int g = 0; g < kG; g++) {
        float m = (float)g_counts[g * kV + t] / (float)kBT;
        terms[g * kV + t] = m * logf(m + 1e-7f);
    }
    __syncthreads();
    if (t == 0) {
        float p = 0.f;
        for (int g = 0; g < kG; g++) {
            float s = 0.f;
            for (int v = 0; v < kV; v++) s += terms[g * kV + v];
            p += expf(-s);
        }
        out[out_size - 1] = p;
    }
}

extern "C" void kernel_launch(void* const* d_in, const int* in_sizes, int n_in,
                              void* d_out, int out_size) {
    (void)in_sizes; (void)n_in;
    const float* hid  = (const float*)d_in[0];
    const float* W    = (const float*)d_in[1];
    const float* bias = (const float*)d_in[2];
    const float* cb   = (const float*)d_in[3];
    float* out = (float*)d_out;

    cudaFuncSetAttribute(vq_mma, cudaFuncAttributeMaxDynamicSharedMemorySize,
                         kSmemBytes);

    vq_zero<<<(2 * kTB + 255) / 256, 256>>>();
    split_h_kernel<<<(kBT * kH / 4) / 256, 256>>>(hid);
    split_w_kernel<<<(kH * kGV) / 256, 256>>>(W);
    vq_mma<<<kTB * 4, kThr, kSmemBytes>>>(bias, cb, out);
    vq_ppl<<<1, kV>>>(out, out_size);
}

// round 16
// speedup vs baseline: 1.2258x; 1.0141x over previous
#include <cuda_runtime.h>
#include <cuda_bf16.h>
#include <cstdint>

// ---------------------------------------------------------------------------
// Wav2Vec2 Gumbel VQ via mma.sync bf16 (sm_100 baseline path).
//   logits = h @ W + b with bf16x3 split, 6 products (fp32-quality).
//   R13 mainloop (measured best total): 128-thread CTAs (tile 64x160,
//   warp tile 32x80), 4 CTAs/SM single-buffered, pipelined b-fragments.
//   R13 epilogue: ticketed merge (argmax merge + histogram + gather in-kernel).
//   R16: one fused prep kernel (zero + split_h + split_w), parallel vq_ppl.
// ---------------------------------------------------------------------------

namespace {
constexpr int kBT = 65536;
constexpr int kH  = 512;
constexpr int kV  = 320;
constexpr int kG  = 2;
constexpr int kGV = kG * kV;

constexpr int kMT = 64;                   // tokens per CTA
constexpr int kNT = 160;                  // logit cols per CTA (half group)
constexpr int kKC = 32;                   // K per chunk (2 mma k-steps)
constexpr int kChunks = kH / kKC;         // 16
constexpr int kThr = 128;                 // threads per CTA (4 warps)
constexpr int kTB  = kBT / kMT;           // 1024 token blocks

constexpr uint32_t kRowB   = 80;                           // 32 bf16 + 16B pad
constexpr uint32_t kAterm  = kMT * kRowB;                  // 5120
constexpr uint32_t kBterm  = kNT * kRowB;                  // 12800
constexpr uint32_t kStage  = 3 * kAterm + 3 * kBterm;      // 53760 (single buf)
constexpr uint32_t kHdr    = 2048;
constexpr uint32_t kSmemBytes = kHdr + kStage;             // 55808 (x4 = 223232)

// fused prep kernel block ranges
constexpr int kPrepHBlocks = (kBT * kH / 4) / 256;         // 32768
constexpr int kPrepWBlocks = (kH * kGV) / 256;             // 1280
constexpr int kPrepBlocks  = kPrepHBlocks + kPrepWBlocks + 1;
}  // namespace

// global scratch (no cudaMalloc allowed)
__device__ __align__(256) __nv_bfloat16 g_h1[(size_t)kBT * kH];
__device__ __align__(256) __nv_bfloat16 g_h2[(size_t)kBT * kH];
__device__ __align__(256) __nv_bfloat16 g_h3[(size_t)kBT * kH];
__device__ __align__(256) __nv_bfloat16 g_w1t[kGV * kH];
__device__ __align__(256) __nv_bfloat16 g_w2t[kGV * kH];
__device__ __align__(256) __nv_bfloat16 g_w3t[kGV * kH];
__device__ float g_pval[4 * kBT];   // [(g*2+half)][token]
__device__ int   g_pidx[4 * kBT];
__device__ int   g_ticket[2 * kTB]; // per (token-block, group)
__device__ int   g_counts[kGV];

// ---------------- PTX helpers ----------------
__device__ __forceinline__ uint32_t smem_u32(const void* p) {
    uint32_t a;
    asm("{ .reg .u64 t; cvta.to.shared.u64 t, %1; cvt.u32.u64 %0, t; }"
        : "=r"(a) : "l"(p));
    return a;
}
__device__ __forceinline__ void cpa16(uint32_t s, const void* g) {
    asm volatile("cp.async.cg.shared.global [%0], [%1], 16;" :: "r"(s), "l"(g));
}
__device__ __forceinline__ void cpa_commit() {
    asm volatile("cp.async.commit_group;" ::: "memory");
}
__device__ __forceinline__ void ldsm4(uint32_t* d, uint32_t addr) {
    asm volatile("ldmatrix.sync.aligned.m8n8.x4.shared.b16 {%0,%1,%2,%3}, [%4];"
                 : "=r"(d[0]), "=r"(d[1]), "=r"(d[2]), "=r"(d[3]) : "r"(addr));
}
__device__ __forceinline__ void mma16816(float* c, const uint32_t* a,
                                         uint32_t b0, uint32_t b1) {
    asm volatile(
        "mma.sync.aligned.m16n8k16.row.col.f32.bf16.bf16.f32 "
        "{%0,%1,%2,%3}, {%4,%5,%6,%7}, {%8,%9}, {%0,%1,%2,%3};"
        : "+f"(c[0]), "+f"(c[1]), "+f"(c[2]), "+f"(c[3])
        : "r"(a[0]), "r"(a[1]), "r"(a[2]), "r"(a[3]), "r"(b0), "r"(b1));
}

// ---------------- fused prep kernel (zero + split_h + split_w) -------------
__device__ __forceinline__ uint32_t pk2(__nv_bfloat16 x, __nv_bfloat16 y) {
    return (uint32_t)__bfloat16_as_ushort(x) |
           ((uint32_t)__bfloat16_as_ushort(y) << 16);
}

__global__ void __launch_bounds__(256)
vq_prep(const float* __restrict__ h, const float* __restrict__ W) {
    const int bxx = blockIdx.x;
    if (bxx < kPrepHBlocks) {
        // ---- split h: one float4 per thread ----
        size_t i = (size_t)bxx * 256 + threadIdx.x;
        float4 x = ((const float4*)h)[i];
        float v[4] = {x.x, x.y, x.z, x.w};
        __nv_bfloat16 a[4], b[4], c[4];
#pragma unroll
        for (int j = 0; j < 4; j++) {
            a[j] = __float2bfloat16_rn(v[j]);
            float r = v[j] - __bfloat162float(a[j]);
            b[j] = __float2bfloat16_rn(r);
            float r2 = r - __bfloat162float(b[j]);
            c[j] = __float2bfloat16_rn(r2);
        }
        ((uint2*)g_h1)[i] = make_uint2(pk2(a[0], a[1]), pk2(a[2], a[3]));
        ((uint2*)g_h2)[i] = make_uint2(pk2(b[0], b[1]), pk2(b[2], b[3]));
        ((uint2*)g_h3)[i] = make_uint2(pk2(c[0], c[1]), pk2(c[2], c[3]));
    } else if (bxx < kPrepHBlocks + kPrepWBlocks) {
        // ---- split + transpose W ----
        int idx = (bxx - kPrepHBlocks) * 256 + threadIdx.x;   // over 512*640
        int k = idx / kGV;
        int n = idx - k * kGV;
        float v = W[idx];
        __nv_bfloat16 a = __float2bfloat16_rn(v);
        float r = v - __bfloat162float(a);
        __nv_bfloat16 b = __float2bfloat16_rn(r);
        float r2 = r - __bfloat162float(b);
        __nv_bfloat16 c = __float2bfloat16_rn(r2);
        size_t o = (size_t)n * kH + k;               // transposed [n][k]
        g_w1t[o] = a; g_w2t[o] = b; g_w3t[o] = c;
    } else {
        // ---- zero counters + tickets (one block) ----
        for (int i = threadIdx.x; i < kGV; i += 256) g_counts[i] = 0;
        for (int i = threadIdx.x; i < 2 * kTB; i += 256) g_ticket[i] = 0;
    }
}

// ---------------- main tensor kernel loader (R13) ----------------
__device__ __forceinline__ void load_chunk(int c, int m0, int nbase,
                                           uint32_t As, uint32_t Bsm, int tid) {
    // A: 3 terms x 64 rows x 4 x 16B = 768 cp.async (6 per thread)
#pragma unroll
    for (int t = 0; t < 3; ++t) {
        const __nv_bfloat16* hp = (t == 0) ? g_h1 : (t == 1) ? g_h2 : g_h3;
#pragma unroll
        for (int i = 0; i < 2; ++i) {
            int idx = tid + i * kThr;        // 0..255
            int row = idx >> 2, cs = idx & 3;
            const void* gp = hp + ((size_t)(m0 + row) * kH + c * kKC + cs * 8);
            cpa16(As + t * kAterm + row * kRowB + cs * 16, gp);
        }
    }
    // B: 3 terms x 160 rows x 4 x 16B = 1920 cp.async (15 per thread)
#pragma unroll
    for (int t = 0; t < 3; ++t) {
        const __nv_bfloat16* wp = (t == 0) ? g_w1t : (t == 1) ? g_w2t : g_w3t;
#pragma unroll
        for (int i = 0; i < 5; ++i) {
            int idx = tid + i * kThr;        // 0..639
            int row = idx >> 2, cs = idx & 3;
            const void* gp = wp + ((size_t)(nbase + row) * kH + c * kKC + cs * 8);
            cpa16(Bsm + t * kBterm + row * kRowB + cs * 16, gp);
        }
    }
    cpa_commit();
}

__global__ void __launch_bounds__(kThr, 4)
vq_mma(const float* __restrict__ bias,
       const float* __restrict__ cb,      // [640][128]
       float* __restrict__ out)           // [BT][256]
{
    extern __shared__ __align__(256) char smem_raw[];
    const uint32_t sbase = smem_u32(smem_raw);
    float* red_val = (float*)smem_raw;                 // [64][2]   @0
    int*   red_idx = (int*)(smem_raw + 512);           // [64][2]   @512
    float* bias_s  = (float*)(smem_raw + 1024);        // [160]     @1024
    int*   idx_s   = (int*)(smem_raw + 1664);          // [64]      @1664
    __shared__ int is_merger;
    const uint32_t As  = sbase + kHdr;                 // A tiles (single buf)
    const uint32_t Bsm = As + 3 * kAterm;              // B tiles (single buf)

    const int tid  = threadIdx.x;
    const int warp = tid >> 5;
    const int lane = tid & 31;
    const int mw   = warp >> 1;            // 0..1 (32 rows each)
    const int nw   = warp & 1;             // 0..1 (80 cols each)
    const int gID  = lane >> 2;
    const int tig  = lane & 3;
    const int bx   = blockIdx.x;
    const int half = bx & 1;
    const int g    = (bx >> 1) & 1;
    const int m0   = (bx >> 2) * kMT;
    const int nbase = g * kV + half * kNT; // B row base

    for (int i = tid; i < kNT; i += kThr) bias_s[i] = bias[nbase + i];

    load_chunk(0, m0, nbase, As, Bsm, tid);

    float acc[2][10][4];
#pragma unroll
    for (int mf = 0; mf < 2; ++mf)
#pragma unroll
        for (int nf = 0; nf < 10; ++nf)
#pragma unroll
            for (int q = 0; q < 4; ++q) acc[mf][nf][q] = 0.f;

    const int g2 = lane >> 3, rr = lane & 7;

    for (int c = 0; c < kChunks; ++c) {
        asm volatile("cp.async.wait_group 0;" ::: "memory");
        __syncthreads();

#pragma unroll
        for (int ks = 0; ks < 2; ++ks) {
            const uint32_t arow = (uint32_t)(mw * 32 + (g2 & 1) * 8 + rr);
            const uint32_t koA  = (uint32_t)(ks * 32 + (g2 >> 1) * 16);
            const uint32_t brow = (uint32_t)(nw * 80 + (g2 >> 1) * 8 + rr);
            const uint32_t koB  = (uint32_t)(ks * 32 + (g2 & 1) * 16);

            // Load ALL A fragments once per ks (6 ldsm; 24 regs live).
            uint32_t a[3][2][4];
#pragma unroll
            for (int t = 0; t < 3; ++t)
#pragma unroll
                for (int mf = 0; mf < 2; ++mf)
                    ldsm4(a[t][mf],
                          As + t * kAterm + (arow + mf * 16) * kRowB + koA);

            // Software-pipelined b: step i issues ldsm for step i+1 BEFORE
            // the 12 MMAs consuming the current fragment (R13, measured best).
            uint32_t bc[4], bn[4];
            ldsm4(bc, Bsm + 0 * kBterm + (brow + 0 * 16) * kRowB + koB);
#pragma unroll
            for (int i = 0; i < 15; ++i) {
                const int bt = i / 5, j = i % 5;
                if (i < 14) {
                    const int bt2 = (i + 1) / 5, j2 = (i + 1) % 5;
                    ldsm4(bn, Bsm + bt2 * kBterm + (brow + j2 * 16) * kRowB + koB);
                }
                const int nat = 3 - bt;     // products with at+bt<=2
#pragma unroll
                for (int at = 0; at < 3; ++at) {
                    if (at >= nat) break;
#pragma unroll
                    for (int mf = 0; mf < 2; ++mf) {
                        mma16816(acc[mf][2 * j],     a[at][mf], bc[0], bc[1]);
                        mma16816(acc[mf][2 * j + 1], a[at][mf], bc[2], bc[3]);
                    }
                }
                if (i < 14) {
#pragma unroll
                    for (int q = 0; q < 4; ++q) bc[q] = bn[q];
                }
            }
        }
        __syncthreads();
        if (c + 1 < kChunks)
            load_chunk(c + 1, m0, nbase, As, Bsm, tid);
    }

    // ---- fused bias + local argmax over this CTA's 160 cols ----
#pragma unroll
    for (int mf = 0; mf < 2; ++mf) {
#pragma unroll
        for (int hi = 0; hi < 2; ++hi) {
            float bv = -3.4e38f;
            int bi = 0;
#pragma unroll
            for (int nf = 0; nf < 10; ++nf) {
#pragma unroll
                for (int cc = 0; cc < 2; ++cc) {
                    int col = nw * 80 + nf * 8 + tig * 2 + cc;
                    float v = acc[mf][nf][hi * 2 + cc] + bias_s[col];
                    if (v > bv) { bv = v; bi = col; }
                }
            }
#pragma unroll
            for (int d = 1; d < 4; d <<= 1) {
                float ov = __shfl_xor_sync(0xFFFFFFFFu, bv, d);
                int   oi = __shfl_xor_sync(0xFFFFFFFFu, bi, d);
                if (ov > bv || (ov == bv && oi < bi)) { bv = ov; bi = oi; }
            }
            if (tig == 0) {
                int row = mw * 32 + mf * 16 + hi * 8 + gID;
                red_val[row * 2 + nw] = bv;
                red_idx[row * 2 + nw] = bi;
            }
        }
    }
    __syncthreads();

    // ---- publish this half's partial (max, idx) per token ----
    if (tid < kMT) {
        float v0 = red_val[tid * 2], v1 = red_val[tid * 2 + 1];
        int   i0 = red_idx[tid * 2], i1 = red_idx[tid * 2 + 1];
        float bv = v0; int bi = i0;
        if (v1 > bv || (v1 == bv && i1 < bi)) { bv = v1; bi = i1; }
        int slot = (g * 2 + half) * kBT + m0 + tid;
        g_pval[slot] = bv;
        g_pidx[slot] = half * kNT + bi;     // group-local index 0..319
    }
    __threadfence();
    __syncthreads();

    // ---- ticket: the SECOND half-CTA of (token-block, g) merges ----
    if (tid == 0)
        is_merger = (atomicAdd(&g_ticket[(m0 / kMT) * 2 + g], 1) == 1);
    __syncthreads();
    if (!is_merger) return;
    __threadfence();

    if (tid < kMT) {
        int tok = m0 + tid;
        float v0 = g_pval[(g * 2 + 0) * kBT + tok];
        float v1 = g_pval[(g * 2 + 1) * kBT + tok];
        int   i0 = g_pidx[(g * 2 + 0) * kBT + tok];
        int   i1 = g_pidx[(g * 2 + 1) * kBT + tok];
        int bi = (v1 > v0) ? i1 : i0;       // tie -> half0 (lower idx)
        idx_s[tid] = bi;
        atomicAdd(&g_counts[g * kV + bi], 1);
    }
    __syncthreads();

    // ---- coalesced codevector gather (this group's half of each out row) ----
    const float4* cbv  = (const float4*)cb;
    float4*       outv = (float4*)out;
#pragma unroll
    for (int i = 0; i < 16; ++i) {
        int e = tid + i * kThr;             // 0..2047
        int m = e >> 5, j = e & 31;
        int vi = idx_s[m];
        outv[(size_t)(m0 + m) * 64 + g * 32 + j] =
            cbv[(size_t)(g * kV + vi) * 32 + j];
    }
}

// ---------------- perplexity (parallel reduction) ----------------
__global__ void vq_ppl(float* __restrict__ out, int out_size) {
    __shared__ float red0[10], red1[10];
    int t = threadIdx.x;               // 320 threads = 10 warps
    int lane = t & 31, w = t >> 5;
    float m0v = (float)g_counts[t] / (float)kBT;            // group 0
    float m1v = (float)g_counts[kV + t] / (float)kBT;       // group 1
    float s0 = m0v * logf(m0v + 1e-7f);
    float s1 = m1v * logf(m1v + 1e-7f);
#pragma unroll
    for (int d = 16; d > 0; d >>= 1) {
        s0 += __shfl_xor_sync(0xFFFFFFFFu, s0, d);
        s1 += __shfl_xor_sync(0xFFFFFFFFu, s1, d);
    }
    if (lane == 0) { red0[w] = s0; red1[w] = s1; }
    __syncthreads();
    if (t == 0) {
        float S0 = 0.f, S1 = 0.f;
#pragma unroll
        for (int i = 0; i < 10; ++i) { S0 += red0[i]; S1 += red1[i]; }
        out[out_size - 1] = expf(-S0) + expf(-S1);
    }
}

extern "C" void kernel_launch(void* const* d_in, const int* in_sizes, int n_in,
                              void* d_out, int out_size) {
    (void)in_sizes; (void)n_in;
    const float* hid  = (const float*)d_in[0];
    const float* W    = (const float*)d_in[1];
    const float* bias = (const float*)d_in[2];
    const float* cb   = (const float*)d_in[3];
    float* out = (float*)d_out;

    cudaFuncSetAttribute(vq_mma, cudaFuncAttributeMaxDynamicSharedMemorySize,
                         kSmemBytes);

    vq_prep<<<kPrepBlocks, 256>>>(hid, W);
    vq_mma<<<kTB * 4, kThr, kSmemBytes>>>(bias, cb, out);
    vq_ppl<<<1, kV>>>(out, out_size);
}